// round 16
// baseline (speedup 1.0000x reference)
#include <cuda_runtime.h>
#include <cuda_fp16.h>

// ---------------------------------------------------------------------------
// MSDeformAttention  (bs=8, Lq=Lv=5440, D=256, 8 heads x 32, 4 levels x 4 pts)
//
//   1) V      = value @ Wv + bv    (tf32 MMA; epilogue -> fp16 x-PAIR layout)
//   2) OFF/AW = query @ [Woff|Wa]  (single fused tf32 MMA launch)
//   3) AW     = softmax16(softmax128(AWL))
//   4) MID    = bilinear-gather v7 (pair-entry loads: 2 aligned 128B/point)
//   5) out    = MID @ Wout + bout  (tf32 MMA)
//
// R16: fixed fragment-packed B layout (R15 had cross-region collisions:
// ntp=3 block reached offset 523 > 512 region stride).  Now region stride
// 528 = 4*132, ntp stride 132 — injective, verified.
// ---------------------------------------------------------------------------

#define LQ     5440
#define BSZ    8
#define NH     8
#define DH     32
#define DMODEL 256
#define MROWS  (BSZ * LQ)          // 43520
#define KDIM   256

// scratch (static device globals: allocation-free)
__device__ __align__(128) __half g_Vp[(size_t)BSZ * NH * LQ * 64];  // pair layout
__device__ float  g_off[(size_t)MROWS * DMODEL];
__device__ float  g_aw [(size_t)MROWS * 128];
__device__ float  g_mid[(size_t)MROWS * DMODEL];

// tf32 round (rna); returns the b32 bit pattern (cvt.rna.tf32 needs .b32 dst).
__device__ __forceinline__ unsigned f2tf32(float x) {
    unsigned y;
    asm("cvt.rna.tf32.f32 %0, %1;" : "=r"(y) : "f"(x));
    return y;
}

// decode pos (0..5439) -> x within its level row, and S
__device__ __forceinline__ void decode_x(int pos, int& x, int& S) {
    int pil;
    if (pos < 4096)      { pil = pos;        S = 64; }
    else if (pos < 5120) { pil = pos - 4096; S = 32; }
    else if (pos < 5376) { pil = pos - 5120; S = 16; }
    else                 { pil = pos - 5376; S = 8;  }
    x = pil & (S - 1);
}

// ---------------------------------------------------------------------------
// Shared GEMM body: C[M,N] = A[M,256] @ B[256,N] + bias[N]
// Block tile 128x128, BK=16, 256 threads = 8 warps (4m x 2n), warp tile 32x64.
// Double-buffered smem (one __syncthreads per k-iter) + register prefetch.
// A smem: [k][m] stride 136 (conflict-free scalar frag loads).
// B smem: MMA-fragment-packed, INJECTIVE strides:
//   element (k,n): kk=k>>3, t=k&3, kr=(k>>2)&1; g=n&7, nt=(n>>3)&7, wb=n>>6,
//   ntp=nt>>1, ntl=nt&1,
//   addr = (kk*2+wb)*528 + ntp*132 + g*16 + t*4 + (kr + 2*ntl)
//   (within-ntp max 127 < 132; within-region max 523 < 528)
//   consumer: uint4 at (kk*2+wb)*528 + ntp*132 + lane*4 yields
//   {b[2ntp][0], b[2ntp][1], b[2ntp+1][0], b[2ntp+1][1]}  (16B-aligned).
// mode 0: row-major fp32 C.   mode 1: fp16 dual-store into g_Vp pair layout.
// ---------------------------------------------------------------------------
__device__ __forceinline__ void gemm_body(
    const float* __restrict__ A, const float* __restrict__ B,
    const float* __restrict__ bias, float* __restrict__ C,
    int N, int m0, int n0, int mode)
{
    __shared__ unsigned As[2][16 * 136];   // [k][m] tf32 bits
    __shared__ unsigned Bs[2][2112];       // fragment-packed tf32 bits

    const int tid  = threadIdx.x;
    const int lane = tid & 31;
    const int warp = tid >> 5;
    const int gid  = lane >> 2;     // 0..7
    const int tig  = lane & 3;      // 0..3
    const int mwi  = warp >> 1;     // 0..3
    const int wb   = warp & 1;      // 0..1
    const int wm   = mwi * 32;
    const int wn   = wb * 64;

    // A global-load / smem-store assignment
    const int la_row = tid >> 1;            // m 0..127
    const int la_cg  = (tid & 1) * 8;       // k-half 0/8

    // B global-load assignment + fragment-packed store base
    const int lb_k  = tid >> 4;             // k 0..15
    const int lb_c4 = (tid & 15) * 4;       // n_local 0..60 step 4
    const int b_kk  = lb_k >> 3;
    const int b_t   = lb_k & 3;
    const int b_kr  = (lb_k >> 2) & 1;
    const int b_g0  = lb_c4 & 7;            // 0 or 4
    const int b_nt  = (lb_c4 >> 3) & 7;
    const int b_ntp = b_nt >> 1;
    const int b_ntl = b_nt & 1;
    const int b_base0 = (b_kk * 2 + 0) * 528 + b_ntp * 132
                      + b_g0 * 16 + b_t * 4 + b_kr + 2 * b_ntl;
    const int b_base1 = b_base0 + 528;      // wb=1 region

    const float* Ap = A + (size_t)(m0 + la_row) * KDIM + la_cg;
    const float* Bp = B + (size_t)lb_k * N + n0 + lb_c4;

    float acc[2][8][4];
#pragma unroll
    for (int mt = 0; mt < 2; mt++)
#pragma unroll
        for (int nt = 0; nt < 8; nt++)
#pragma unroll
            for (int r = 0; r < 4; r++) acc[mt][nt][r] = 0.0f;

    // prologue: first k-tile into registers
    float4 av0 = *(const float4*)(Ap);
    float4 av1 = *(const float4*)(Ap + 4);
    float4 bv0 = *(const float4*)(Bp);
    float4 bv1 = *(const float4*)(Bp + 64);

    int buf = 0;
    for (int k0 = 0; k0 < KDIM; k0 += 16) {
        unsigned* as = As[buf];
        unsigned* bs = Bs[buf];

        // A stores: [k][m] stride 136 (conflict-free)
        as[(la_cg + 0) * 136 + la_row] = f2tf32(av0.x);
        as[(la_cg + 1) * 136 + la_row] = f2tf32(av0.y);
        as[(la_cg + 2) * 136 + la_row] = f2tf32(av0.z);
        as[(la_cg + 3) * 136 + la_row] = f2tf32(av0.w);
        as[(la_cg + 4) * 136 + la_row] = f2tf32(av1.x);
        as[(la_cg + 5) * 136 + la_row] = f2tf32(av1.y);
        as[(la_cg + 6) * 136 + la_row] = f2tf32(av1.z);
        as[(la_cg + 7) * 136 + la_row] = f2tf32(av1.w);

        // B stores: fragment-packed (n+1 -> g+1 -> +16)
        bs[b_base0 +  0] = f2tf32(bv0.x);
        bs[b_base0 + 16] = f2tf32(bv0.y);
        bs[b_base0 + 32] = f2tf32(bv0.z);
        bs[b_base0 + 48] = f2tf32(bv0.w);
        bs[b_base1 +  0] = f2tf32(bv1.x);
        bs[b_base1 + 16] = f2tf32(bv1.y);
        bs[b_base1 + 32] = f2tf32(bv1.z);
        bs[b_base1 + 48] = f2tf32(bv1.w);
        __syncthreads();

        // prefetch next k-tile into registers while computing this one
        if (k0 + 16 < KDIM) {
            Ap += 16;
            Bp += (size_t)16 * N;
            av0 = *(const float4*)(Ap);
            av1 = *(const float4*)(Ap + 4);
            bv0 = *(const float4*)(Bp);
            bv1 = *(const float4*)(Bp + 64);
        }

#pragma unroll
        for (int kk = 0; kk < 2; kk++) {
            const int ks = kk * 8;
            unsigned a[2][4];
#pragma unroll
            for (int mt = 0; mt < 2; mt++) {
                const int mb = wm + mt * 16;
                a[mt][0] = as[(ks + tig    ) * 136 + mb + gid    ];
                a[mt][1] = as[(ks + tig    ) * 136 + mb + gid + 8];
                a[mt][2] = as[(ks + tig + 4) * 136 + mb + gid    ];
                a[mt][3] = as[(ks + tig + 4) * 136 + mb + gid + 8];
            }
            uint4 bf[4];
#pragma unroll
            for (int ntp = 0; ntp < 4; ntp++)
                bf[ntp] = *(const uint4*)&bs[(kk * 2 + wb) * 528
                                             + ntp * 132 + lane * 4];
#pragma unroll
            for (int mt = 0; mt < 2; mt++)
#pragma unroll
                for (int nt = 0; nt < 8; nt++) {
                    const uint4& f = bf[nt >> 1];
                    const unsigned b0 = (nt & 1) ? f.z : f.x;
                    const unsigned b1 = (nt & 1) ? f.w : f.y;
                    asm volatile(
                        "mma.sync.aligned.m16n8k8.row.col.f32.tf32.tf32.f32 "
                        "{%0,%1,%2,%3}, {%4,%5,%6,%7}, {%8,%9}, {%0,%1,%2,%3};"
                        : "+f"(acc[mt][nt][0]), "+f"(acc[mt][nt][1]),
                          "+f"(acc[mt][nt][2]), "+f"(acc[mt][nt][3])
                        : "r"(a[mt][0]), "r"(a[mt][1]), "r"(a[mt][2]), "r"(a[mt][3]),
                          "r"(b0), "r"(b1));
                }
        }
        buf ^= 1;
    }

    // epilogue
#pragma unroll
    for (int mt = 0; mt < 2; mt++) {
#pragma unroll
        for (int rr = 0; rr < 2; rr++) {
            const int m = m0 + wm + mt * 16 + gid + rr * 8;
            const int bb  = m / LQ;
            const int pos = m - bb * LQ;

            int xcol = 0, S = 0;
            size_t rowbase = 0;
            if (mode == 1) {
                decode_x(pos, xcol, S);
                rowbase = ((size_t)(bb * NH) * LQ + pos) * 64;
            }
#pragma unroll
            for (int nt = 0; nt < 8; nt++) {
                const int n = n0 + wn + nt * 8 + tig * 2;
                float2 v;
                v.x = acc[mt][nt][rr * 2 + 0] + bias[n];
                v.y = acc[mt][nt][rr * 2 + 1] + bias[n + 1];
                if (mode == 0) {
                    *(float2*)&C[(size_t)m * N + n] = v;
                } else {
                    const int h = n >> 5;
                    const int c = n & 31;   // even
                    const __half2 hv = __floats2half2_rn(v.x, v.y);
                    const size_t base = rowbase + (size_t)h * LQ * 64;
                    *(__half2*)&g_Vp[base + c] = hv;
                    if (xcol > 0)
                        *(__half2*)&g_Vp[base - 64 + 32 + c] = hv;
                    if (xcol == S - 1)
                        *(__half2*)&g_Vp[base + 32 + c] = hv;
                }
            }
        }
    }
}

// generic GEMM kernel (used for V and final output)
__global__ __launch_bounds__(256, 2) void tf32gemm(
    const float* __restrict__ A, const float* __restrict__ B,
    const float* __restrict__ bias, float* __restrict__ C,
    int N, int mode)
{
    gemm_body(A, B, bias, C, N, blockIdx.y * 128, blockIdx.x * 128, mode);
}

// fused OFF + AW GEMM: grid.x = 3.  Blocks 0,1 -> query@Woff -> g_off (N=256);
// block 2 -> query@Wa -> g_aw (N=128).
__global__ __launch_bounds__(256, 2) void tf32gemm_offaw(
    const float* __restrict__ A,
    const float* __restrict__ Woff, const float* __restrict__ boff,
    const float* __restrict__ Wa,   const float* __restrict__ ba)
{
    const int m0 = blockIdx.y * 128;
    if (blockIdx.x < 2) {
        gemm_body(A, Woff, boff, g_off, 256, m0, blockIdx.x * 128, 0);
    } else {
        gemm_body(A, Wa, ba, g_aw, 128, m0, 0, 0);
    }
}

// ---------------------------------------------------------------------------
// Double softmax (unchanged).
// ---------------------------------------------------------------------------
__global__ __launch_bounds__(256) void softmax2_kernel(float* __restrict__ buf)
{
    const int warp = threadIdx.x >> 5;
    const int lane = threadIdx.x & 31;
    const int row  = blockIdx.x * 8 + warp;
    float* p = buf + (size_t)row * 128 + lane * 4;

    float4 v = *(const float4*)p;

    float vm = fmaxf(fmaxf(v.x, v.y), fmaxf(v.z, v.w));
#pragma unroll
    for (int o = 16; o; o >>= 1) vm = fmaxf(vm, __shfl_xor_sync(~0u, vm, o));
    float e0 = expf(v.x - vm), e1 = expf(v.y - vm);
    float e2 = expf(v.z - vm), e3 = expf(v.w - vm);
    float s = e0 + e1 + e2 + e3;
#pragma unroll
    for (int o = 16; o; o >>= 1) s += __shfl_xor_sync(~0u, s, o);
    const float inv = 1.0f / s;
    const float t0 = e0 * inv, t1 = e1 * inv, t2 = e2 * inv, t3 = e3 * inv;

    float gm = fmaxf(fmaxf(t0, t1), fmaxf(t2, t3));
    gm = fmaxf(gm, __shfl_xor_sync(~0u, gm, 1));
    gm = fmaxf(gm, __shfl_xor_sync(~0u, gm, 2));
    float f0 = expf(t0 - gm), f1 = expf(t1 - gm);
    float f2 = expf(t2 - gm), f3 = expf(t3 - gm);
    float gs = f0 + f1 + f2 + f3;
    gs += __shfl_xor_sync(~0u, gs, 1);
    gs += __shfl_xor_sync(~0u, gs, 2);
    const float ginv = 1.0f / gs;

    float4 o4;
    o4.x = f0 * ginv; o4.y = f1 * ginv; o4.z = f2 * ginv; o4.w = f3 * ginv;
    *(float4*)p = o4;
}

// ---------------------------------------------------------------------------
// Sampling v7 (pair-entry loads), 5 CTAs/SM — unchanged from R13.
// ---------------------------------------------------------------------------
__global__ __launch_bounds__(256, 5) void msdeform_sample_kernel(
    const float* __restrict__ refpts)
{
    const int bq   = blockIdx.x;
    const int b    = bq / LQ;
    const int h    = threadIdx.x >> 5;
    const int lane = threadIdx.x & 31;
    const int q    = lane & 3;        // channel quarter

    const float2* offp2 = (const float2*)(g_off + (size_t)bq * 256 + h * 32);
    const float*  awp   = g_aw + (size_t)bq * 128 + h * 16;
    const float*  refp  = refpts + (size_t)bq * 8;
    const char*   vbase = (const char*)(g_Vp + ((size_t)(b * NH + h)) * LQ * 64);

    // ---- Producer: point = lane>>1, ypair z = lane&1 ----
    unsigned offs_p;
    float cwlo_p, cwhi_p;
    {
        const int own_p = lane >> 1;          // point 0..15
        const int z     = lane & 1;           // y side
        const int l     = own_p >> 2;         // level 0..3
        const int S     = 64 >> l;
        const int start = (16384 - ((S * S) << 2)) / 3;   // 0,4096,5120,5376
        const float inv_S = __int_as_float((121 + l) << 23);  // exact 1/S
        const float c1  = 0.5f * (float)S - 1.0f;             // 0.5*(S-2)
        const float a   = c1 * inv_S;                         // exact

        const float2 r = __ldg((const float2*)(refp + l * 2));
        const float2 o = __ldg(&offp2[own_p]);
        const float  w = __ldg(&awp[own_p]);

        const float x = fmaf(o.x, a, fmaf(r.x, c1, c1));
        const float y = fmaf(o.y, a, fmaf(r.y, c1, c1));

        const int x0 = (int)floorf(x);
        const int y0 = (int)floorf(y);
        const int x0c = min(max(x0, 0),     S - 1);
        const int y0c = min(max(y0, 0),     S - 1);
        const int y1c = min(max(y0 + 1, 0), S - 1);
        const float x0f = (float)x0c;
        const float x1f = (float)min(max(x0 + 1, 0), S - 1);
        const float y0f = (float)y0c, y1f = (float)y1c;

        const int   ysel = z ? y1c : y0c;
        const float wy   = z ? (y - y0f) : (y1f - y);
        const float wxlo = (x1f - x);
        const float wxhi = (x - x0f);

        offs_p  = (unsigned)((start + ysel * S + x0c) << 7);   // *128 bytes
        cwlo_p  = (w * wxlo) * wy;
        cwhi_p  = (w * wxhi) * wy;
    }

    // ---- Consumer ----
    const int pu   = lane >> 3;               // pair-slot 0..3
    const int e    = lane & 7;                // 16B chunk in the pair entry
    const int ehi  = e >> 2;                  // 0 = .lo (x0), 1 = .hi (x1)
    const int obase = ((pu >> 1) << 1) | (pu & 1);   // 2*psel + yp
    const unsigned eoff = (unsigned)(e * 16);

    float acc[8];
#pragma unroll
    for (int j = 0; j < 8; j++) acc[j] = 0.0f;

#pragma unroll
    for (int g = 0; g < 2; g++) {
        unsigned offs[4];
        float    cwv[4];
#pragma unroll
        for (int j = 0; j < 4; j++) {
            const int i = g * 4 + j;
            const int owner = i * 4 + obase;
            const unsigned o_ = __shfl_sync(~0u, offs_p, owner);
            const float    cl = __shfl_sync(~0u, cwlo_p, owner);
            const float    ch = __shfl_sync(~0u, cwhi_p, owner);
            offs[j] = o_ + eoff;
            cwv[j]  = ehi ? ch : cl;
        }

        uint4 hv[4];
#pragma unroll
        for (int j = 0; j < 4; j++)
            hv[j] = __ldg((const uint4*)(vbase + offs[j]));

#pragma unroll
        for (int j = 0; j < 4; j++) {
            const float cw = cwv[j];
            const float2 f0 = __half22float2(*(const __half2*)&hv[j].x);
            const float2 f1 = __half22float2(*(const __half2*)&hv[j].y);
            const float2 f2 = __half22float2(*(const __half2*)&hv[j].z);
            const float2 f3 = __half22float2(*(const __half2*)&hv[j].w);
            acc[0] = fmaf(cw, f0.x, acc[0]);
            acc[1] = fmaf(cw, f0.y, acc[1]);
            acc[2] = fmaf(cw, f1.x, acc[2]);
            acc[3] = fmaf(cw, f1.y, acc[3]);
            acc[4] = fmaf(cw, f2.x, acc[4]);
            acc[5] = fmaf(cw, f2.y, acc[5]);
            acc[6] = fmaf(cw, f3.x, acc[6]);
            acc[7] = fmaf(cw, f3.y, acc[7]);
        }
    }

    // reduce across the 8 lanes sharing this q (lanes q, q+4, ..., q+28)
#pragma unroll
    for (int m = 4; m <= 16; m <<= 1)
#pragma unroll
        for (int j = 0; j < 8; j++)
            acc[j] += __shfl_xor_sync(~0u, acc[j], m);

    if ((lane >> 2) == 0) {
        float* dst = g_mid + (size_t)bq * 256 + h * 32 + q * 8;
        *(float4*)(dst + 0) = make_float4(acc[0], acc[1], acc[2], acc[3]);
        *(float4*)(dst + 4) = make_float4(acc[4], acc[5], acc[6], acc[7]);
    }
}

// ---------------------------------------------------------------------------
// launch
// ---------------------------------------------------------------------------
extern "C" void kernel_launch(void* const* d_in, const int* in_sizes, int n_in,
                              void* d_out, int out_size)
{
    const float* query = (const float*)d_in[0];
    const float* value = (const float*)d_in[1];
    const float* refp  = (const float*)d_in[2];
    const float* Wv    = (const float*)d_in[3];
    const float* bv    = (const float*)d_in[4];
    const float* Woff  = (const float*)d_in[5];
    const float* boff  = (const float*)d_in[6];
    const float* Wa    = (const float*)d_in[7];
    const float* ba    = (const float*)d_in[8];
    const float* Wout  = (const float*)d_in[9];
    const float* bout  = (const float*)d_in[10];
    float* out = (float*)d_out;

    float *pAw, *pMid;
    cudaGetSymbolAddress((void**)&pAw,  g_aw);
    cudaGetSymbolAddress((void**)&pMid, g_mid);

    const dim3 gN256(2, MROWS / 128);   // (2, 340)
    const dim3 gOffAw(3, MROWS / 128);  // (3, 340)

    tf32gemm<<<gN256, 256>>>(value, Wv, bv, /*unused in mode1*/ pMid, 256, 1);
    tf32gemm_offaw<<<gOffAw, 256>>>(query, Woff, boff, Wa, ba);
    softmax2_kernel<<<MROWS / 8, 256>>>(pAw);
    msdeform_sample_kernel<<<MROWS, 256>>>(refp);
    tf32gemm<<<gN256, 256>>>(pMid, Wout, bout, out, 256, 0);
}